// round 3
// baseline (speedup 1.0000x reference)
#include <cuda_runtime.h>
#include <cuda_bf16.h>

// PatchShuffle: T=1024 (16 rows x 64 cols), B=64, C=768, STRIPE_W=48.
// Outputs concatenated as float32:
//   visible       [256*64*768]   gather of shuffled rows 0..255
//   fwd           [1024*64]      forward permutation indices (as float)
//   bwd           [1024*64]      inverse permutation indices (as float)
//   stripe_bounds [2*64]         {start, start+48} per batch
//
// perm(b, j) closed form (stable argsort of col + 64*in_stripe):
//   s = start[b]
//   j <  s        -> j            (non-stripe cols below stripe)
//   s <= j < 16   -> j + 48       (non-stripe cols above stripe)
//   j >= 16       -> s + (j-16)   (stripe cols, in order)
// inverse:
//   col <  s        -> col
//   s <= col < s+48 -> 16 + (col - s)
//   col >= s+48     -> col - 48

#define NUM_ROWS   16
#define NUM_COLS   64
#define STRIPE_W   48
#define B_         64
#define C_         768
#define C4_        192                       // 768 floats = 192 float4
#define T_VIS      256                       // min_visible / ... rows 0..3, all 64 cols
#define T_ALL      1024

#define N_VIS4     (T_VIS * B_ * C4_)        // 3,145,728 float4 items
#define OFF_FWD    (T_VIS * B_ * C_)         // 12,582,912 floats
#define N_FWD      (T_ALL * B_)              // 65,536
#define OFF_BWD    (OFF_FWD + N_FWD)
#define OFF_SB     (OFF_BWD + N_FWD)
#define N_TOTAL    (N_VIS4 + 2 * N_FWD + 128)

__device__ __forceinline__ int perm_of(int s, int j) {
    // forward permutation: position j -> source column
    return (j < s) ? j : ((j < 16) ? (j + STRIPE_W) : (s + (j - 16)));
}

__device__ __forceinline__ int inv_of(int s, int col) {
    // inverse permutation: source column -> position
    return (col < s) ? col : ((col < s + STRIPE_W) ? (16 + (col - s)) : (col - STRIPE_W));
}

__global__ void __launch_bounds__(256)
patchshuffle_kernel(const float4* __restrict__ patches,
                    const int*    __restrict__ start_cols,
                    float*        __restrict__ out) {
    int idx = blockIdx.x * blockDim.x + threadIdx.x;

    if (idx < N_VIS4) {
        // ---- visible gather: one float4 per thread, contiguous in C ----
        int c4   = idx % C4_;
        int pair = idx / C4_;              // t*64 + b
        int b    = pair & 63;
        int t    = pair >> 6;              // 0..255
        int row  = t >> 6;                 // 0..3
        int j    = t & 63;                 // position within row
        int s    = __ldg(start_cols + b);
        int p    = perm_of(s, j);
        int src_t = (row << 6) + p;        // source token index
        // patches[src_t][b][c] : contiguous 192 float4 per (t,b)
        float4 v = patches[(src_t * B_ + b) * C4_ + c4];
        reinterpret_cast<float4*>(out)[idx] = v;
        return;
    }

    int r = idx - N_VIS4;
    if (r < N_FWD) {
        // ---- fwd[t][b] ----
        int t   = r >> 6;
        int b   = r & 63;
        int row = t >> 6;
        int j   = t & 63;
        int s   = __ldg(start_cols + b);
        out[OFF_FWD + r] = (float)((row << 6) + perm_of(s, j));
        return;
    }
    r -= N_FWD;
    if (r < N_FWD) {
        // ---- bwd[i][b] (inverse permutation, per-row) ----
        int i   = r >> 6;
        int b   = r & 63;
        int row = i >> 6;
        int col = i & 63;
        int s   = __ldg(start_cols + b);
        out[OFF_BWD + r] = (float)((row << 6) + inv_of(s, col));
        return;
    }
    r -= N_FWD;
    if (r < 128) {
        // ---- stripe_bounds[2][64] ----
        int b = r & 63;
        int s = __ldg(start_cols + b);
        out[OFF_SB + r] = (float)((r < 64) ? s : (s + STRIPE_W));
    }
}

extern "C" void kernel_launch(void* const* d_in, const int* in_sizes, int n_in,
                              void* d_out, int out_size) {
    const float4* patches    = (const float4*)d_in[0];
    const int*    start_cols = (const int*)d_in[1];
    float*        out        = (float*)d_out;

    int threads = 256;
    int blocks  = (N_TOTAL + threads - 1) / threads;   // 12801
    patchshuffle_kernel<<<blocks, threads>>>(patches, start_cols, out);
}

// round 5
// speedup vs baseline: 1.2973x; 1.2973x over previous
#include <cuda_runtime.h>
#include <cuda_bf16.h>

// PatchShuffle: T=1024 (16 rows x 64 cols), B=64, C=768, STRIPE_W=48.
// Outputs concatenated as float32:
//   visible       [256*64*768]   gather of shuffled rows 0..255
//   fwd           [1024*64]      forward permutation indices (as float)
//   bwd           [1024*64]      inverse permutation indices (as float)
//   stripe_bounds [2*64]         {start, start+48} per batch
//
// perm(b, j) closed form (stable argsort of col + 64*in_stripe):
//   s = start[b]
//   j <  s        -> j
//   s <= j < 16   -> j + 48
//   j >= 16       -> s + (j-16)
// inverse:
//   col <  s        -> col
//   s <= col < s+48 -> 16 + (col - s)
//   col >= s+48     -> col - 48

#define STRIPE_W   48
#define B_         64
#define C_         768
#define C4_        192
#define T_VIS      256
#define T_ALL      1024

#define N_VIS4     (T_VIS * B_ * C4_)        // 3,145,728 float4 items
#define OFF_FWD    (T_VIS * B_ * C_)         // 12,582,912 floats
#define N_FWD      (T_ALL * B_)              // 65,536
#define OFF_BWD    (OFF_FWD + N_FWD)
#define OFF_SB     (OFF_BWD + N_FWD)

#define ILP        4
#define THREADS    256
#define VIS_BLOCKS (N_VIS4 / (THREADS * ILP))    // 3072 exactly
#define VIS_STRIDE (VIS_BLOCKS * THREADS)        // 786,432
#define N_TAIL     (2 * N_FWD + 128)             // 131,200
#define TAIL_BLOCKS ((N_TAIL + THREADS - 1) / THREADS)  // 513

__device__ __forceinline__ int perm_of(int s, int j) {
    return (j < s) ? j : ((j < 16) ? (j + STRIPE_W) : (s + (j - 16)));
}

__device__ __forceinline__ int inv_of(int s, int col) {
    return (col < s) ? col : ((col < s + STRIPE_W) ? (16 + (col - s)) : (col - STRIPE_W));
}

__global__ void __launch_bounds__(THREADS)
patchshuffle_kernel(const float4* __restrict__ patches,
                    const int*    __restrict__ start_cols,
                    float*        __restrict__ out) {
    int bid = blockIdx.x;
    int tid = threadIdx.x;

    if (bid < VIS_BLOCKS) {
        // ---- visible gather: 4 independent float4 per thread ----
        int base = bid * THREADS + tid;
        float4 v[ILP];
        #pragma unroll
        for (int k = 0; k < ILP; k++) {
            int idx  = base + k * VIS_STRIDE;   // always < N_VIS4 (exact fit)
            int c4   = idx % C4_;
            int pair = idx / C4_;               // t*64 + b
            int b    = pair & 63;
            int t    = pair >> 6;               // 0..255
            int row  = t >> 6;                  // 0..3
            int j    = t & 63;                  // position within row
            int s    = __ldg(start_cols + b);
            int p    = perm_of(s, j);
            v[k] = patches[(((row << 6) + p) * B_ + b) * C4_ + c4];
        }
        float4* o4 = reinterpret_cast<float4*>(out);
        #pragma unroll
        for (int k = 0; k < ILP; k++)
            __stcs(o4 + base + k * VIS_STRIDE, v[k]);   // evict-first: keep reads in L2
        return;
    }

    // ---- tail: index outputs, one element per thread ----
    int r = (bid - VIS_BLOCKS) * THREADS + tid;
    if (r < N_FWD) {
        // fwd[t][b]
        int t   = r >> 6;
        int b   = r & 63;
        int row = t >> 6;
        int j   = t & 63;
        int s   = __ldg(start_cols + b);
        out[OFF_FWD + r] = (float)((row << 6) + perm_of(s, j));
        return;
    }
    r -= N_FWD;
    if (r < N_FWD) {
        // bwd[i][b]
        int i   = r >> 6;
        int b   = r & 63;
        int row = i >> 6;
        int col = i & 63;
        int s   = __ldg(start_cols + b);
        out[OFF_BWD + r] = (float)((row << 6) + inv_of(s, col));
        return;
    }
    r -= N_FWD;
    if (r < 128) {
        // stripe_bounds[2][64]
        int b = r & 63;
        int s = __ldg(start_cols + b);
        out[OFF_SB + r] = (float)((r < 64) ? s : (s + STRIPE_W));
    }
}

extern "C" void kernel_launch(void* const* d_in, const int* in_sizes, int n_in,
                              void* d_out, int out_size) {
    const float4* patches    = (const float4*)d_in[0];
    const int*    start_cols = (const int*)d_in[1];
    float*        out        = (float*)d_out;

    patchshuffle_kernel<<<VIS_BLOCKS + TAIL_BLOCKS, THREADS>>>(patches, start_cols, out);
}